// round 1
// baseline (speedup 1.0000x reference)
#include <cuda_runtime.h>
#include <math.h>

// Problem constants
#define BSZ 4
#define CC  64
#define OC  64
#define HH  128
#define WW  128
#define HW  (HH*WW)        // 16384
#define KK  9
#define NPIX (BSZ*HW)      // 65536

// __device__ scratch (allocation-free rule: static device globals)
__device__ float g_x_nhwc[BSZ*HH*WW*CC];   // 16 MB, [b][h][w][c]
__device__ float g_off[BSZ*27*HW];         // 7 MB,  [b][j][h][w]
__device__ float g_w_ro[OC*CC*KK];         // [o][k*64+c], BN-scale folded
__device__ float g_beff[OC];               // folded bias

// ---------------------------------------------------------------------------
// Kernel A: NCHW -> NHWC transpose of x
// ---------------------------------------------------------------------------
__global__ void k_transpose(const float* __restrict__ x) {
    int idx = blockIdx.x * blockDim.x + threadIdx.x;  // over B*C*H*W = 4M
    if (idx >= BSZ*CC*HW) return;
    int w = idx & (WW-1);
    int h = (idx >> 7) & (HH-1);
    int c = (idx >> 14) & (CC-1);
    int b = idx >> 20;
    g_x_nhwc[((b*HH + h)*WW + w)*CC + c] = x[idx];
}

// ---------------------------------------------------------------------------
// Kernel R: fold BN into weights, reorder weight [o][c][k] -> [o][k*64+c]
// ---------------------------------------------------------------------------
__global__ void k_reorder(const float* __restrict__ weight, const float* __restrict__ bias,
                          const float* __restrict__ gamma, const float* __restrict__ beta,
                          const float* __restrict__ rmean, const float* __restrict__ rvar) {
    int idx = blockIdx.x * blockDim.x + threadIdx.x;
    if (idx < OC) {
        float s = gamma[idx] * rsqrtf(rvar[idx] + 1e-5f);
        g_beff[idx] = (bias[idx] - rmean[idx]) * s + beta[idx];
    }
    if (idx >= OC*CC*KK) return;
    int k = idx % 9;
    int c = (idx / 9) & (CC-1);
    int o = idx / (CC*KK);
    float s = gamma[o] * rsqrtf(rvar[o] + 1e-5f);
    g_w_ro[o*(CC*KK) + k*CC + c] = weight[idx] * s;
}

// ---------------------------------------------------------------------------
// Kernel B: offset conv (3x3, pad 1) producing 27 channels per pixel.
// One thread = one pixel, all 27 output channels in registers (padded to 28
// for float4). w_off staged in shared as [c][t][j(28)].
// ---------------------------------------------------------------------------
#define OB_THREADS 256
__global__ void k_offconv(const float* __restrict__ x, const float* __restrict__ w_off,
                          const float* __restrict__ b_off) {
    extern __shared__ float sw[];  // 64*9*28 floats = 64512 B
    for (int i = threadIdx.x; i < 27*CC*9; i += OB_THREADS) {
        int t = i % 9;
        int c = (i / 9) & (CC-1);
        int j = i / (CC*9);
        sw[(c*9 + t)*28 + j] = w_off[i];
    }
    for (int i = threadIdx.x; i < CC*9; i += OB_THREADS) sw[i*28 + 27] = 0.f;
    __syncthreads();

    int pix = blockIdx.x * OB_THREADS + threadIdx.x;   // over 65536
    int w = pix & (WW-1);
    int h = (pix >> 7) & (HH-1);
    int b = pix >> 14;

    // per-tap validity + offsets (pad=1)
    int  offs[9];
    bool valv[9];
#pragma unroll
    for (int t = 0; t < 9; t++) {
        int dy = t/3 - 1, dx = t%3 - 1;
        int yy = h + dy, xx = w + dx;
        valv[t] = (yy >= 0) && (yy < HH) && (xx >= 0) && (xx < WW);
        offs[t] = yy*WW + xx;
    }

    float4 acc[7];
#pragma unroll
    for (int q = 0; q < 7; q++) acc[q] = make_float4(0.f,0.f,0.f,0.f);

    const float* xb = x + (size_t)b*CC*HW;
    for (int c = 0; c < CC; c++) {
        float xv[9];
#pragma unroll
        for (int t = 0; t < 9; t++)
            xv[t] = valv[t] ? xb[c*HW + offs[t]] : 0.f;
#pragma unroll
        for (int t = 0; t < 9; t++) {
            const float4* wrow = (const float4*)&sw[(c*9 + t)*28];
            float xvt = xv[t];
#pragma unroll
            for (int q = 0; q < 7; q++) {
                float4 wv = wrow[q];
                acc[q].x = fmaf(xvt, wv.x, acc[q].x);
                acc[q].y = fmaf(xvt, wv.y, acc[q].y);
                acc[q].z = fmaf(xvt, wv.z, acc[q].z);
                acc[q].w = fmaf(xvt, wv.w, acc[q].w);
            }
        }
    }

    const float* accf = (const float*)acc;
    int pbase = h*WW + w;
#pragma unroll
    for (int j = 0; j < 27; j++) {
        g_off[(b*27 + j)*HW + pbase] = accf[j] + b_off[j];  // coalesced over w
    }
}

// ---------------------------------------------------------------------------
// Kernel C: deformable sampling + matvec + BN bias + ReLU
// Block = 32 consecutive pixels (same b, h row). 256 threads.
// Phase 1: warp-per-(pixel,tap) bilinear gather into shared (mask folded).
// Phase 2: [32 pix] x [64 out] matvec over K=576, chunked by tap (k).
// ---------------------------------------------------------------------------
#define PPB 32
#define CT  256
__global__ void k_dcn(float* __restrict__ out) {
    extern __shared__ float sh[];
    float* s_off  = sh;                    // 27*32  = 864 floats
    float* s_samp = sh + 864;              // 32*576 = 18432 floats
    float* s_w    = sh + 864 + 18432;      // 64*64  = 4096 floats ([cc][n])

    int tid = threadIdx.x;
    int gp0 = blockIdx.x * PPB;            // all 32 pixels share (b, h)
    int b  = gp0 >> 14;
    int h  = (gp0 >> 7) & (HH-1);
    int w0 = gp0 & (WW-1);

    // load offsets for the 32 pixels: [j][p], coalesced over p
    for (int i = tid; i < 27*PPB; i += CT) {
        int j = i >> 5;
        int p = i & 31;
        s_off[i] = g_off[(b*27 + j)*HW + h*WW + w0 + p];
    }
    __syncthreads();

    // Phase 1: gather. 288 (pixel, tap) tasks over 8 warps.
    {
        int warp = tid >> 5;
        int lane = tid & 31;
        const float* xb = g_x_nhwc + (size_t)b*HW*CC;
        for (int t = warp; t < PPB*KK; t += 8) {
            int p = t / KK;
            int k = t - p*KK;
            float oy = s_off[(2*k)*PPB + p];
            float ox = s_off[(2*k+1)*PPB + p];
            float mv = 1.f / (1.f + expf(-s_off[(18+k)*PPB + p]));
            float py = (float)(h + k/3 - 1) + oy;
            float px = (float)(w0 + p + k%3 - 1) + ox;
            float y0f = floorf(py), x0f = floorf(px);
            float dy = py - y0f, dx = px - x0f;
            int y0 = (int)y0f, x0 = (int)x0f;
            int y1 = y0 + 1,  x1 = x0 + 1;
            bool vy0 = (y0 >= 0) && (y0 < HH);
            bool vy1 = (y1 >= 0) && (y1 < HH);
            bool vx0 = (x0 >= 0) && (x0 < WW);
            bool vx1 = (x1 >= 0) && (x1 < WW);
            float w00 = (1.f-dy)*(1.f-dx)*mv;
            float w01 = (1.f-dy)*dx*mv;
            float w10 = dy*(1.f-dx)*mv;
            float w11 = dy*dx*mv;

            float ax = 0.f, ay = 0.f;
            int c2 = 2*lane;
            if (vy0 && vx0) {
                float2 v = *(const float2*)&xb[(y0*WW + x0)*CC + c2];
                ax = fmaf(w00, v.x, ax); ay = fmaf(w00, v.y, ay);
            }
            if (vy0 && vx1) {
                float2 v = *(const float2*)&xb[(y0*WW + x1)*CC + c2];
                ax = fmaf(w01, v.x, ax); ay = fmaf(w01, v.y, ay);
            }
            if (vy1 && vx0) {
                float2 v = *(const float2*)&xb[(y1*WW + x0)*CC + c2];
                ax = fmaf(w10, v.x, ax); ay = fmaf(w10, v.y, ay);
            }
            if (vy1 && vx1) {
                float2 v = *(const float2*)&xb[(y1*WW + x1)*CC + c2];
                ax = fmaf(w11, v.x, ax); ay = fmaf(w11, v.y, ay);
            }
            *(float2*)&s_samp[p*576 + k*CC + c2] = make_float2(ax, ay);
        }
    }
    __syncthreads();

    // Phase 2: matvec. thread -> out channel n = tid&63, pixel group mg = tid>>6.
    int n  = tid & 63;
    int mg = tid >> 6;           // 0..3 -> pixels 8*mg .. 8*mg+7
    float acc[8];
#pragma unroll
    for (int i = 0; i < 8; i++) acc[i] = 0.f;

    for (int kc = 0; kc < 9; kc++) {
        // stage weight chunk as s_w[cc][n]
        for (int i = tid; i < 1024; i += CT) {     // i over float4s
            int o  = i >> 4;
            int c4 = i & 15;
            float4 wv = *(const float4*)(g_w_ro + o*576 + kc*64 + c4*4);
            int base = (c4*4)*64 + o;
            s_w[base]       = wv.x;
            s_w[base + 64]  = wv.y;
            s_w[base + 128] = wv.z;
            s_w[base + 192] = wv.w;
        }
        __syncthreads();
#pragma unroll 4
        for (int cc = 0; cc < 64; cc += 4) {
            float wa = s_w[(cc+0)*64 + n];
            float wb = s_w[(cc+1)*64 + n];
            float wc = s_w[(cc+2)*64 + n];
            float wd = s_w[(cc+3)*64 + n];
#pragma unroll
            for (int i = 0; i < 8; i++) {
                float4 s4 = *(const float4*)(s_samp + (8*mg + i)*576 + kc*64 + cc);
                acc[i] = fmaf(wa, s4.x, fmaf(wb, s4.y, fmaf(wc, s4.z, fmaf(wd, s4.w, acc[i]))));
            }
        }
        __syncthreads();
    }

    // BN bias + ReLU, float4 stores (NCHW output)
    float bv = g_beff[n];
    float r[8];
#pragma unroll
    for (int i = 0; i < 8; i++) r[i] = fmaxf(acc[i] + bv, 0.f);
    float* op = out + ((size_t)(b*OC + n))*HW + h*WW + w0 + 8*mg;
    *(float4*)(op)     = make_float4(r[0], r[1], r[2], r[3]);
    *(float4*)(op + 4) = make_float4(r[4], r[5], r[6], r[7]);
}

// ---------------------------------------------------------------------------
extern "C" void kernel_launch(void* const* d_in, const int* in_sizes, int n_in,
                              void* d_out, int out_size) {
    const float* x      = (const float*)d_in[0];
    const float* w_off  = (const float*)d_in[1];
    const float* b_off  = (const float*)d_in[2];
    const float* weight = (const float*)d_in[3];
    const float* bias   = (const float*)d_in[4];
    const float* gamma  = (const float*)d_in[5];
    const float* beta   = (const float*)d_in[6];
    const float* rmean  = (const float*)d_in[7];
    const float* rvar   = (const float*)d_in[8];
    float* out = (float*)d_out;

    (void)in_sizes; (void)n_in; (void)out_size;

    const int smem_off = 64*9*28*4;                     // 64512 B
    const int smem_dcn = (864 + 18432 + 4096) * 4;      // 93568 B
    cudaFuncSetAttribute(k_offconv, cudaFuncAttributeMaxDynamicSharedMemorySize, smem_off);
    cudaFuncSetAttribute(k_dcn,     cudaFuncAttributeMaxDynamicSharedMemorySize, smem_dcn);

    k_transpose<<<(BSZ*CC*HW + 255)/256, 256>>>(x);
    k_reorder<<<(OC*CC*KK + 255)/256, 256>>>(weight, bias, gamma, beta, rmean, rvar);
    k_offconv<<<NPIX/OB_THREADS, OB_THREADS, smem_off>>>(x, w_off, b_off);
    k_dcn<<<NPIX/PPB, CT, smem_dcn>>>(out);
}

// round 5
// speedup vs baseline: 1.4991x; 1.4991x over previous
#include <cuda_runtime.h>
#include <math.h>

// Problem constants
#define BSZ 4
#define CC  64
#define OC  64
#define HH  128
#define WW  128
#define HW  (HH*WW)        // 16384
#define KK  9
#define NPIX (BSZ*HW)      // 65536

// __device__ scratch (allocation-free rule: static device globals)
__device__ float g_x_nhwc[BSZ*HH*WW*CC];   // 16 MB, [b][h][w][c]
__device__ float g_off[BSZ*27*HW];         // 7 MB,  [b][j][h][w]
__device__ float g_w_t[KK*CC*OC];          // [k][c][o], BN-scale folded (transposed)
__device__ float g_beff[OC];               // folded bias

// ---------------------------------------------------------------------------
// Kernel A: NCHW -> NHWC transpose of x, tiled through shared (conflict-free)
// One block per (b,h): transposes the [C=64][W=128] plane to [W][C].
// ---------------------------------------------------------------------------
#define TP_THREADS 256
__global__ void k_transpose(const float* __restrict__ x) {
    __shared__ float tile[CC * (WW + 1)];   // pad stride 129 -> conflict-free
    int bh = blockIdx.x;                    // 0..511
    int b = bh >> 7;
    int h = bh & (HH-1);
    const float* xp = x + ((size_t)(b*CC)*HH + h)*WW;   // + c*HH*WW + w
    // load: coalesced over w
    for (int i = threadIdx.x; i < CC*WW; i += TP_THREADS) {
        int c = i >> 7;
        int w = i & (WW-1);
        tile[c*(WW+1) + w] = xp[(size_t)c*HW + w];
    }
    __syncthreads();
    // store: coalesced over c
    float* op = g_x_nhwc + ((size_t)(b*HH + h)*WW)*CC;
    for (int i = threadIdx.x; i < CC*WW; i += TP_THREADS) {
        int c = i & (CC-1);
        int w = i >> 6;
        op[w*CC + c] = tile[c*(WW+1) + w];
    }
}

// ---------------------------------------------------------------------------
// Kernel R: fold BN into weights, transpose weight [o][c][k] -> [k][c][o]
// ---------------------------------------------------------------------------
__global__ void k_reorder(const float* __restrict__ weight, const float* __restrict__ bias,
                          const float* __restrict__ gamma, const float* __restrict__ beta,
                          const float* __restrict__ rmean, const float* __restrict__ rvar) {
    int idx = blockIdx.x * blockDim.x + threadIdx.x;
    if (idx < OC) {
        float s = gamma[idx] * rsqrtf(rvar[idx] + 1e-5f);
        g_beff[idx] = (bias[idx] - rmean[idx]) * s + beta[idx];
    }
    if (idx >= OC*CC*KK) return;
    int k = idx % 9;
    int c = (idx / 9) & (CC-1);
    int o = idx / (CC*KK);
    float s = gamma[o] * rsqrtf(rvar[o] + 1e-5f);
    g_w_t[(k*CC + c)*OC + o] = weight[idx] * s;
}

// ---------------------------------------------------------------------------
// Kernel B: offset conv (3x3, pad 1) producing 27 channels per pixel.
// One thread = one pixel, all 27 output channels in registers (padded to 28
// for float4). w_off staged in shared as [c][t][j(28)].
// ---------------------------------------------------------------------------
#define OB_THREADS 256
__global__ void k_offconv(const float* __restrict__ x, const float* __restrict__ w_off,
                          const float* __restrict__ b_off) {
    extern __shared__ float sw[];  // 64*9*28 floats = 64512 B
    for (int i = threadIdx.x; i < 27*CC*9; i += OB_THREADS) {
        int t = i % 9;
        int c = (i / 9) & (CC-1);
        int j = i / (CC*9);
        sw[(c*9 + t)*28 + j] = w_off[i];
    }
    for (int i = threadIdx.x; i < CC*9; i += OB_THREADS) sw[i*28 + 27] = 0.f;
    __syncthreads();

    int pix = blockIdx.x * OB_THREADS + threadIdx.x;   // over 65536
    int w = pix & (WW-1);
    int h = (pix >> 7) & (HH-1);
    int b = pix >> 14;

    int  offs[9];
    bool valv[9];
#pragma unroll
    for (int t = 0; t < 9; t++) {
        int dy = t/3 - 1, dx = t%3 - 1;
        int yy = h + dy, xx = w + dx;
        valv[t] = (yy >= 0) && (yy < HH) && (xx >= 0) && (xx < WW);
        offs[t] = yy*WW + xx;
    }

    float4 acc[7];
#pragma unroll
    for (int q = 0; q < 7; q++) acc[q] = make_float4(0.f,0.f,0.f,0.f);

    const float* xb = x + (size_t)b*CC*HW;
    for (int c = 0; c < CC; c++) {
        float xv[9];
#pragma unroll
        for (int t = 0; t < 9; t++)
            xv[t] = valv[t] ? xb[c*HW + offs[t]] : 0.f;
#pragma unroll
        for (int t = 0; t < 9; t++) {
            const float4* wrow = (const float4*)&sw[(c*9 + t)*28];
            float xvt = xv[t];
#pragma unroll
            for (int q = 0; q < 7; q++) {
                float4 wv = wrow[q];
                acc[q].x = fmaf(xvt, wv.x, acc[q].x);
                acc[q].y = fmaf(xvt, wv.y, acc[q].y);
                acc[q].z = fmaf(xvt, wv.z, acc[q].z);
                acc[q].w = fmaf(xvt, wv.w, acc[q].w);
            }
        }
    }

    const float* accf = (const float*)acc;
    int pbase = h*WW + w;
#pragma unroll
    for (int j = 0; j < 27; j++) {
        g_off[(b*27 + j)*HW + pbase] = accf[j] + b_off[j];  // coalesced over w
    }
}

// ---------------------------------------------------------------------------
// Kernel C: deformable sampling + matvec + BN bias + ReLU
// Block = 32 consecutive pixels (same b, h row). 256 threads.
// Phase 1: warp-per-(pixel,tap) bilinear gather into shared (mask folded).
// Phase 2: [32 pix] x [64 out] matvec over K=576. Weights read straight from
// global ([k][c][o] layout -> conflict-free per-lane o, L1/L2 resident).
// samp reads are warp-broadcast (1 wavefront each). ONE barrier total.
// ---------------------------------------------------------------------------
#define PPB 32
#define CT  256
__global__ void __launch_bounds__(CT, 2) k_dcn(float* __restrict__ out) {
    extern __shared__ float sh[];
    float* s_off  = sh;                    // 27*32  = 864 floats
    float* s_samp = sh + 864;              // 32*576 = 18432 floats

    int tid = threadIdx.x;
    int gp0 = blockIdx.x * PPB;            // all 32 pixels share (b, h)
    int b  = gp0 >> 14;
    int h  = (gp0 >> 7) & (HH-1);
    int w0 = gp0 & (WW-1);

    // load offsets for the 32 pixels: [j][p], coalesced over p
    for (int i = tid; i < 27*PPB; i += CT) {
        int j = i >> 5;
        int p = i & 31;
        s_off[i] = g_off[(b*27 + j)*HW + h*WW + w0 + p];
    }
    __syncthreads();

    // Phase 1: gather. 288 (pixel, tap) tasks over 8 warps.
    {
        int warp = tid >> 5;
        int lane = tid & 31;
        const float* xb = g_x_nhwc + (size_t)b*HW*CC;
        for (int t = warp; t < PPB*KK; t += 8) {
            int p = t / KK;
            int k = t - p*KK;
            float oy = s_off[(2*k)*PPB + p];
            float ox = s_off[(2*k+1)*PPB + p];
            float mv = 1.f / (1.f + __expf(-s_off[(18+k)*PPB + p]));
            float py = (float)(h + k/3 - 1) + oy;
            float px = (float)(w0 + p + k%3 - 1) + ox;
            float y0f = floorf(py), x0f = floorf(px);
            float dy = py - y0f, dx = px - x0f;
            int y0 = (int)y0f, x0 = (int)x0f;
            int y1 = y0 + 1,  x1 = x0 + 1;
            bool vy0 = (y0 >= 0) && (y0 < HH);
            bool vy1 = (y1 >= 0) && (y1 < HH);
            bool vx0 = (x0 >= 0) && (x0 < WW);
            bool vx1 = (x1 >= 0) && (x1 < WW);
            float w00 = (1.f-dy)*(1.f-dx)*mv;
            float w01 = (1.f-dy)*dx*mv;
            float w10 = dy*(1.f-dx)*mv;
            float w11 = dy*dx*mv;

            float ax = 0.f, ay = 0.f;
            int c2 = 2*lane;
            if (vy0 && vx0) {
                float2 v = *(const float2*)&xb[(y0*WW + x0)*CC + c2];
                ax = fmaf(w00, v.x, ax); ay = fmaf(w00, v.y, ay);
            }
            if (vy0 && vx1) {
                float2 v = *(const float2*)&xb[(y0*WW + x1)*CC + c2];
                ax = fmaf(w01, v.x, ax); ay = fmaf(w01, v.y, ay);
            }
            if (vy1 && vx0) {
                float2 v = *(const float2*)&xb[(y1*WW + x0)*CC + c2];
                ax = fmaf(w10, v.x, ax); ay = fmaf(w10, v.y, ay);
            }
            if (vy1 && vx1) {
                float2 v = *(const float2*)&xb[(y1*WW + x1)*CC + c2];
                ax = fmaf(w11, v.x, ax); ay = fmaf(w11, v.y, ay);
            }
            *(float2*)&s_samp[p*576 + k*CC + c2] = make_float2(ax, ay);
        }
    }
    __syncthreads();

    // Phase 2: matvec. Warp layout: lanes = 32 consecutive out-channels,
    // warp pair -> n half; mg = warp>>1 selects the 8-pixel group.
    int n  = tid & 63;           // lanes within a warp have consecutive n
    int mg = tid >> 6;           // 0..3 -> pixels 8*mg .. 8*mg+7
    float acc[8];
#pragma unroll
    for (int i = 0; i < 8; i++) acc[i] = 0.f;

    const float* samp_base = s_samp + (8*mg)*576;
    for (int kc = 0; kc < 9; kc++) {
        const float* wp = g_w_t + kc*CC*OC + n;   // [c][o], lane-consecutive o
        const float* sp = samp_base + kc*CC;
#pragma unroll 4
        for (int cc = 0; cc < 64; cc += 4) {
            float wa = __ldg(wp + (cc+0)*OC);
            float wb = __ldg(wp + (cc+1)*OC);
            float wc = __ldg(wp + (cc+2)*OC);
            float wd = __ldg(wp + (cc+3)*OC);
#pragma unroll
            for (int i = 0; i < 8; i++) {
                float4 s4 = *(const float4*)(sp + i*576 + cc);   // warp broadcast
                acc[i] = fmaf(wa, s4.x, fmaf(wb, s4.y, fmaf(wc, s4.z, fmaf(wd, s4.w, acc[i]))));
            }
        }
    }

    // BN bias + ReLU, float4 stores (NCHW output)
    float bv = __ldg(g_beff + n);
    float r[8];
#pragma unroll
    for (int i = 0; i < 8; i++) r[i] = fmaxf(acc[i] + bv, 0.f);
    float* op = out + ((size_t)(b*OC + n))*HW + h*WW + w0 + 8*mg;
    *(float4*)(op)     = make_float4(r[0], r[1], r[2], r[3]);
    *(float4*)(op + 4) = make_float4(r[4], r[5], r[6], r[7]);
}

// ---------------------------------------------------------------------------
extern "C" void kernel_launch(void* const* d_in, const int* in_sizes, int n_in,
                              void* d_out, int out_size) {
    const float* x      = (const float*)d_in[0];
    const float* w_off  = (const float*)d_in[1];
    const float* b_off  = (const float*)d_in[2];
    const float* weight = (const float*)d_in[3];
    const float* bias   = (const float*)d_in[4];
    const float* gamma  = (const float*)d_in[5];
    const float* beta   = (const float*)d_in[6];
    const float* rmean  = (const float*)d_in[7];
    const float* rvar   = (const float*)d_in[8];
    float* out = (float*)d_out;

    (void)in_sizes; (void)n_in; (void)out_size;

    const int smem_off = 64*9*28*4;                     // 64512 B
    const int smem_dcn = (864 + 18432) * 4;             // 77184 B
    cudaFuncSetAttribute(k_offconv, cudaFuncAttributeMaxDynamicSharedMemorySize, smem_off);
    cudaFuncSetAttribute(k_dcn,     cudaFuncAttributeMaxDynamicSharedMemorySize, smem_dcn);

    k_transpose<<<BSZ*HH, TP_THREADS>>>(x);
    k_reorder<<<(OC*CC*KK + 255)/256, 256>>>(weight, bias, gamma, beta, rmean, rvar);
    k_offconv<<<NPIX/OB_THREADS, OB_THREADS, smem_off>>>(x, w_off, b_off);
    k_dcn<<<NPIX/PPB, CT, smem_dcn>>>(out);
}

// round 11
// speedup vs baseline: 2.2501x; 1.5010x over previous
#include <cuda_runtime.h>
#include <cuda_bf16.h>
#include <math.h>
#include <stdint.h>

// Problem constants
#define BSZ 4
#define CC  64
#define OC  64
#define HH  128
#define WW  128
#define HW  (HH*WW)        // 16384
#define KK  9
#define NPIX (BSZ*HW)      // 65536

// __device__ scratch (allocation-free rule: static device globals)
__device__ float g_x_nhwc[BSZ*HH*WW*CC];   // 16 MB, [b][h][w][c]
__device__ float g_off[BSZ*27*HW];         // 7 MB,  [b][j][h][w]
// Weights pre-packed in m16n8k16 B-fragment order, split-bf16:
// g_wBf[((kc*4 + kt)*8 + nt)*32 + lane] = {bh0, bh1, bl0, bl1}
__device__ uint4 g_wBf[KK*4*8*32];         // 147456 B
__device__ float g_beff[OC];               // folded bias

// ---------------------------------------------------------------------------
// mma.sync m16n8k16 bf16 (PTX baseline, works under compute_103)
// ---------------------------------------------------------------------------
__device__ __forceinline__ void mma16816(float* c, const uint32_t* a,
                                         uint32_t b0, uint32_t b1) {
    asm volatile(
        "mma.sync.aligned.m16n8k16.row.col.f32.bf16.bf16.f32 "
        "{%0,%1,%2,%3}, {%4,%5,%6,%7}, {%8,%9}, {%0,%1,%2,%3};"
        : "+f"(c[0]), "+f"(c[1]), "+f"(c[2]), "+f"(c[3])
        : "r"(a[0]), "r"(a[1]), "r"(a[2]), "r"(a[3]), "r"(b0), "r"(b1));
}

// ---------------------------------------------------------------------------
// Kernel A: NCHW -> NHWC transpose of x, tiled through shared (conflict-free)
// ---------------------------------------------------------------------------
#define TP_THREADS 256
__global__ void k_transpose(const float* __restrict__ x) {
    __shared__ float tile[CC * (WW + 1)];
    int bh = blockIdx.x;
    int b = bh >> 7;
    int h = bh & (HH-1);
    const float* xp = x + ((size_t)(b*CC)*HH + h)*WW;
    for (int i = threadIdx.x; i < CC*WW; i += TP_THREADS) {
        int c = i >> 7;
        int w = i & (WW-1);
        tile[c*(WW+1) + w] = xp[(size_t)c*HW + w];
    }
    __syncthreads();
    float* op = g_x_nhwc + ((size_t)(b*HH + h)*WW)*CC;
    for (int i = threadIdx.x; i < CC*WW; i += TP_THREADS) {
        int c = i & (CC-1);
        int w = i >> 6;
        op[w*CC + c] = tile[c*(WW+1) + w];
    }
}

// ---------------------------------------------------------------------------
// Kernel R: fold BN into weights, split to bf16 hi/lo, pack into B-fragment
// order for mma.m16n8k16 (col-major B, n = nt*8 + lane/4, k = kt*16 + ...).
// ---------------------------------------------------------------------------
__global__ void k_reorder(const float* __restrict__ weight, const float* __restrict__ bias,
                          const float* __restrict__ gamma, const float* __restrict__ beta,
                          const float* __restrict__ rmean, const float* __restrict__ rvar) {
    int idx = blockIdx.x * blockDim.x + threadIdx.x;
    if (idx < OC) {
        float s = gamma[idx] * rsqrtf(rvar[idx] + 1e-5f);
        g_beff[idx] = (bias[idx] - rmean[idx]) * s + beta[idx];
    }
    if (idx >= KK*4*8*32) return;
    int T  = idx & 31;
    int nt = (idx >> 5) & 7;
    int kt = (idx >> 8) & 3;
    int kc = idx >> 10;
    int t = T & 3, g = T >> 2;
    int o = nt*8 + g;
    float s = gamma[o] * rsqrtf(rvar[o] + 1e-5f);
    int c0 = kt*16 + 2*t;
    float w0 = weight[((size_t)o*CC + c0    )*KK + kc] * s;
    float w1 = weight[((size_t)o*CC + c0 + 1)*KK + kc] * s;
    float w2 = weight[((size_t)o*CC + c0 + 8)*KK + kc] * s;
    float w3 = weight[((size_t)o*CC + c0 + 9)*KK + kc] * s;
    __nv_bfloat162 h0 = __floats2bfloat162_rn(w0, w1);
    __nv_bfloat162 h1 = __floats2bfloat162_rn(w2, w3);
    __nv_bfloat162 l0 = __floats2bfloat162_rn(w0 - __bfloat162float(h0.x),
                                              w1 - __bfloat162float(h0.y));
    __nv_bfloat162 l1 = __floats2bfloat162_rn(w2 - __bfloat162float(h1.x),
                                              w3 - __bfloat162float(h1.y));
    uint4 v;
    v.x = *(uint32_t*)&h0;
    v.y = *(uint32_t*)&h1;
    v.z = *(uint32_t*)&l0;
    v.w = *(uint32_t*)&l1;
    g_wBf[idx] = v;
}

// ---------------------------------------------------------------------------
// Kernel B: offset conv (3x3, pad 1) producing 27 channels per pixel.
// ---------------------------------------------------------------------------
#define OB_THREADS 256
__global__ void k_offconv(const float* __restrict__ x, const float* __restrict__ w_off,
                          const float* __restrict__ b_off) {
    extern __shared__ float sw[];  // 64*9*28 floats
    for (int i = threadIdx.x; i < 27*CC*9; i += OB_THREADS) {
        int t = i % 9;
        int c = (i / 9) & (CC-1);
        int j = i / (CC*9);
        sw[(c*9 + t)*28 + j] = w_off[i];
    }
    for (int i = threadIdx.x; i < CC*9; i += OB_THREADS) sw[i*28 + 27] = 0.f;
    __syncthreads();

    int pix = blockIdx.x * OB_THREADS + threadIdx.x;
    int w = pix & (WW-1);
    int h = (pix >> 7) & (HH-1);
    int b = pix >> 14;

    int  offs[9];
    bool valv[9];
#pragma unroll
    for (int t = 0; t < 9; t++) {
        int dy = t/3 - 1, dx = t%3 - 1;
        int yy = h + dy, xx = w + dx;
        valv[t] = (yy >= 0) && (yy < HH) && (xx >= 0) && (xx < WW);
        offs[t] = yy*WW + xx;
    }

    float4 acc[7];
#pragma unroll
    for (int q = 0; q < 7; q++) acc[q] = make_float4(0.f,0.f,0.f,0.f);

    const float* xb = x + (size_t)b*CC*HW;
    for (int c = 0; c < CC; c++) {
        float xv[9];
#pragma unroll
        for (int t = 0; t < 9; t++)
            xv[t] = valv[t] ? xb[c*HW + offs[t]] : 0.f;
#pragma unroll
        for (int t = 0; t < 9; t++) {
            const float4* wrow = (const float4*)&sw[(c*9 + t)*28];
            float xvt = xv[t];
#pragma unroll
            for (int q = 0; q < 7; q++) {
                float4 wv = wrow[q];
                acc[q].x = fmaf(xvt, wv.x, acc[q].x);
                acc[q].y = fmaf(xvt, wv.y, acc[q].y);
                acc[q].z = fmaf(xvt, wv.z, acc[q].z);
                acc[q].w = fmaf(xvt, wv.w, acc[q].w);
            }
        }
    }

    const float* accf = (const float*)acc;
    int pbase = h*WW + w;
#pragma unroll
    for (int j = 0; j < 27; j++) {
        g_off[(b*27 + j)*HW + pbase] = accf[j] + b_off[j];
    }
}

// ---------------------------------------------------------------------------
// Kernel C: deformable sampling + warp-level bf16 HMMA GEMM + epilogue.
// One CTA per (b,h) row = 128 pixels, 8 warps x 16 pixels. Warps are fully
// independent: NO __syncthreads. Per tap kc:
//   gather+modulate+split-bf16 -> warp-private swizzled SMEM A tile (16x64)
//   -> LDS A fragments -> 96 mma.m16n8k16 against fragment-packed weights.
// SMEM: warp w: A tiles hi/lo at w*4096 (2KB each); s_off at 32768 + w*1792.
// ---------------------------------------------------------------------------
#define CT 256
#define SMEM_DCN (32768 + 8*1792)   // 47104 B

__global__ void __launch_bounds__(CT, 2) k_dcn(float* __restrict__ out) {
    extern __shared__ char smem[];
    int tid = threadIdx.x;
    int wid = tid >> 5;
    int lane = tid & 31;
    int bh = blockIdx.x;
    int b = bh >> 7;
    int h = bh & (HH-1);
    int wp0 = wid * 16;                        // warp's first pixel (w coord)

    char* Ah = smem + wid*4096;
    char* Al = Ah + 2048;
    float* s_off = (float*)(smem + 32768 + wid*1792);

    // warp-private offset load: 27 taps x 16 pixels
    {
        const float* gofs = g_off + (size_t)(b*27)*HW + h*WW + wp0;
        for (int i = lane; i < 27*16; i += 32) {
            int j = i >> 4;
            int p = i & 15;
            s_off[i] = gofs[(size_t)j*HW + p];
        }
    }
    __syncwarp();

    int t = lane & 3, g = lane >> 2;
    float acc[8][4];
#pragma unroll
    for (int nt = 0; nt < 8; nt++)
#pragma unroll
        for (int q = 0; q < 4; q++) acc[nt][q] = 0.f;

    const float* xb = g_x_nhwc + (size_t)b*HW*CC;
    const int c2 = 2*lane;

    for (int kc = 0; kc < 9; kc++) {
        int kr = kc/3 - 1, kx = kc%3 - 1;
        // ---- gather + modulate + split-bf16 into swizzled A tile ----
#pragma unroll 4
        for (int p = 0; p < 16; p++) {
            float oy = s_off[(2*kc)*16 + p];
            float ox = s_off[(2*kc+1)*16 + p];
            float mv = 1.f / (1.f + __expf(-s_off[(18+kc)*16 + p]));
            float py = (float)(h + kr) + oy;
            float px = (float)(wp0 + p + kx) + ox;
            float y0f = floorf(py), x0f = floorf(px);
            float dy = py - y0f, dx = px - x0f;
            int y0 = (int)y0f, x0 = (int)x0f;
            int y1 = y0 + 1,  x1 = x0 + 1;
            bool vy0 = (y0 >= 0) && (y0 < HH);
            bool vy1 = (y1 >= 0) && (y1 < HH);
            bool vx0 = (x0 >= 0) && (x0 < WW);
            bool vx1 = (x1 >= 0) && (x1 < WW);
            float w00 = (1.f-dy)*(1.f-dx)*mv;
            float w01 = (1.f-dy)*dx*mv;
            float w10 = dy*(1.f-dx)*mv;
            float w11 = dy*dx*mv;

            float ax = 0.f, ay = 0.f;
            if (vy0 && vx0) {
                float2 v = *(const float2*)&xb[(y0*WW + x0)*CC + c2];
                ax = fmaf(w00, v.x, ax); ay = fmaf(w00, v.y, ay);
            }
            if (vy0 && vx1) {
                float2 v = *(const float2*)&xb[(y0*WW + x1)*CC + c2];
                ax = fmaf(w01, v.x, ax); ay = fmaf(w01, v.y, ay);
            }
            if (vy1 && vx0) {
                float2 v = *(const float2*)&xb[(y1*WW + x0)*CC + c2];
                ax = fmaf(w10, v.x, ax); ay = fmaf(w10, v.y, ay);
            }
            if (vy1 && vx1) {
                float2 v = *(const float2*)&xb[(y1*WW + x1)*CC + c2];
                ax = fmaf(w11, v.x, ax); ay = fmaf(w11, v.y, ay);
            }
            __nv_bfloat162 hp = __floats2bfloat162_rn(ax, ay);
            __nv_bfloat162 lp = __floats2bfloat162_rn(ax - __bfloat162float(hp.x),
                                                      ay - __bfloat162float(hp.y));
            uint32_t sw = (uint32_t)(lane*4) ^ (uint32_t)((p & 7) << 4);
            *(uint32_t*)(Ah + p*128 + sw) = *(uint32_t*)&hp;
            *(uint32_t*)(Al + p*128 + sw) = *(uint32_t*)&lp;
        }
        __syncwarp();

        // ---- load A fragments (swizzle-matched, conflict-free LDS.32) ----
        uint32_t ah[4][4], al[4][4];
#pragma unroll
        for (int kt = 0; kt < 4; kt++) {
            uint32_t col0 = (uint32_t)(kt*32 + 4*t);
            uint32_t sw0 = col0 ^ (uint32_t)(g << 4);
            uint32_t sw2 = (col0 + 16) ^ (uint32_t)(g << 4);
            ah[kt][0] = *(const uint32_t*)(Ah + g*128 + sw0);
            ah[kt][1] = *(const uint32_t*)(Ah + (g+8)*128 + sw0);
            ah[kt][2] = *(const uint32_t*)(Ah + g*128 + sw2);
            ah[kt][3] = *(const uint32_t*)(Ah + (g+8)*128 + sw2);
            al[kt][0] = *(const uint32_t*)(Al + g*128 + sw0);
            al[kt][1] = *(const uint32_t*)(Al + (g+8)*128 + sw0);
            al[kt][2] = *(const uint32_t*)(Al + g*128 + sw2);
            al[kt][3] = *(const uint32_t*)(Al + (g+8)*128 + sw2);
        }
        __syncwarp();   // allow next kc's stores after all lanes read

        // ---- 3-pass split-bf16 MMA against fragment-packed weights ----
        const uint4* wb = g_wBf + (size_t)kc*1024 + lane;
#pragma unroll
        for (int nt = 0; nt < 8; nt++) {
#pragma unroll
            for (int kt = 0; kt < 4; kt++) {
                uint4 bf = __ldg(wb + (kt*8 + nt)*32);
                mma16816(acc[nt], ah[kt], bf.x, bf.y);   // Ah*Bh
                mma16816(acc[nt], al[kt], bf.x, bf.y);   // Al*Bh
                mma16816(acc[nt], ah[kt], bf.z, bf.w);   // Ah*Bl
            }
        }
    }

    // ---- epilogue: bias + ReLU, direct STG (NCHW) ----
    float* ob = out + (size_t)b*OC*HW + h*WW + wp0 + g;
#pragma unroll
    for (int nt = 0; nt < 8; nt++) {
        int n0 = nt*8 + 2*t;
        float b0 = __ldg(g_beff + n0);
        float b1 = __ldg(g_beff + n0 + 1);
        ob[(size_t)n0*HW]         = fmaxf(acc[nt][0] + b0, 0.f);
        ob[(size_t)(n0+1)*HW]     = fmaxf(acc[nt][1] + b1, 0.f);
        ob[(size_t)n0*HW + 8]     = fmaxf(acc[nt][2] + b0, 0.f);
        ob[(size_t)(n0+1)*HW + 8] = fmaxf(acc[nt][3] + b1, 0.f);
    }
}

// ---------------------------------------------------------------------------
extern "C" void kernel_launch(void* const* d_in, const int* in_sizes, int n_in,
                              void* d_out, int out_size) {
    const float* x      = (const float*)d_in[0];
    const float* w_off  = (const float*)d_in[1];
    const float* b_off  = (const float*)d_in[2];
    const float* weight = (const float*)d_in[3];
    const float* bias   = (const float*)d_in[4];
    const float* gamma  = (const float*)d_in[5];
    const float* beta   = (const float*)d_in[6];
    const float* rmean  = (const float*)d_in[7];
    const float* rvar   = (const float*)d_in[8];
    float* out = (float*)d_out;

    (void)in_sizes; (void)n_in; (void)out_size;

    const int smem_off = 64*9*28*4;       // 64512 B
    cudaFuncSetAttribute(k_offconv, cudaFuncAttributeMaxDynamicSharedMemorySize, smem_off);
    cudaFuncSetAttribute(k_dcn,     cudaFuncAttributeMaxDynamicSharedMemorySize, SMEM_DCN);

    k_transpose<<<BSZ*HH, TP_THREADS>>>(x);
    k_reorder<<<(KK*4*8*32 + 255)/256, 256>>>(weight, bias, gamma, beta, rmean, rvar);
    k_offconv<<<NPIX/OB_THREADS, OB_THREADS, smem_off>>>(x, w_off, b_off);
    k_dcn<<<BSZ*HH, CT, SMEM_DCN>>>(out);
}

// round 15
// speedup vs baseline: 2.6819x; 1.1919x over previous
#include <cuda_runtime.h>
#include <cuda_bf16.h>
#include <math.h>
#include <stdint.h>

// Problem constants
#define BSZ 4
#define CC  64
#define OC  64
#define HH  128
#define WW  128
#define HW  (HH*WW)        // 16384
#define KK  9
#define NPIX (BSZ*HW)      // 65536

// __device__ scratch (allocation-free rule: static device globals)
__device__ float g_x_nhwc[BSZ*HH*WW*CC];   // 16 MB, [b][h][w][c]
// Main conv weights in m16n8k16 B-fragment order, split-bf16:
// g_wBf[((kc*4 + kt)*8 + nt)*32 + lane] = {bh0, bh1, bl0, bl1}
__device__ uint4 g_wBf[KK*4*8*32];         // 147456 B
// Offset-conv weights, same fragment packing, N padded 27->32 (nt 0..3)
__device__ uint4 g_wOf[KK*4*4*32];         // 73728 B
__device__ float g_beff[OC];               // folded bias

// ---------------------------------------------------------------------------
// mma.sync m16n8k16 bf16 (PTX baseline, works under compute_103)
// ---------------------------------------------------------------------------
__device__ __forceinline__ void mma16816(float* c, const uint32_t* a,
                                         uint32_t b0, uint32_t b1) {
    asm volatile(
        "mma.sync.aligned.m16n8k16.row.col.f32.bf16.bf16.f32 "
        "{%0,%1,%2,%3}, {%4,%5,%6,%7}, {%8,%9}, {%0,%1,%2,%3};"
        : "+f"(c[0]), "+f"(c[1]), "+f"(c[2]), "+f"(c[3])
        : "r"(a[0]), "r"(a[1]), "r"(a[2]), "r"(a[3]), "r"(b0), "r"(b1));
}

// ---------------------------------------------------------------------------
// Kernel A: NCHW -> NHWC transpose of x, tiled through shared (conflict-free)
// ---------------------------------------------------------------------------
#define TP_THREADS 256
__global__ void k_transpose(const float* __restrict__ x) {
    __shared__ float tile[CC * (WW + 1)];
    int bh = blockIdx.x;
    int b = bh >> 7;
    int h = bh & (HH-1);
    const float* xp = x + ((size_t)(b*CC)*HH + h)*WW;
    for (int i = threadIdx.x; i < CC*WW; i += TP_THREADS) {
        int c = i >> 7;
        int w = i & (WW-1);
        tile[c*(WW+1) + w] = xp[(size_t)c*HW + w];
    }
    __syncthreads();
    float* op = g_x_nhwc + ((size_t)(b*HH + h)*WW)*CC;
    for (int i = threadIdx.x; i < CC*WW; i += TP_THREADS) {
        int c = i & (CC-1);
        int w = i >> 6;
        op[w*CC + c] = tile[c*(WW+1) + w];
    }
}

// ---------------------------------------------------------------------------
// Kernel R: fold BN into main weights + pack both weight sets into
// m16n8k16 B-fragment order (col-major B), split-bf16 hi/lo.
//   idx in [0, 9216): main conv   (kc, kt, nt0..7, lane)
//   idx in [9216, 13824): offset conv (kc, kt, nt0..3, lane), o>=27 -> 0
// ---------------------------------------------------------------------------
__global__ void k_reorder(const float* __restrict__ weight, const float* __restrict__ bias,
                          const float* __restrict__ gamma, const float* __restrict__ beta,
                          const float* __restrict__ rmean, const float* __restrict__ rvar,
                          const float* __restrict__ w_off) {
    int idx = blockIdx.x * blockDim.x + threadIdx.x;
    if (idx < OC) {
        float s = gamma[idx] * rsqrtf(rvar[idx] + 1e-5f);
        g_beff[idx] = (bias[idx] - rmean[idx]) * s + beta[idx];
    }
    if (idx < KK*4*8*32) {
        int T  = idx & 31;
        int nt = (idx >> 5) & 7;
        int kt = (idx >> 8) & 3;
        int kc = idx >> 10;
        int t = T & 3, g = T >> 2;
        int o = nt*8 + g;
        float s = gamma[o] * rsqrtf(rvar[o] + 1e-5f);
        int c0 = kt*16 + 2*t;
        float w0 = weight[((size_t)o*CC + c0    )*KK + kc] * s;
        float w1 = weight[((size_t)o*CC + c0 + 1)*KK + kc] * s;
        float w2 = weight[((size_t)o*CC + c0 + 8)*KK + kc] * s;
        float w3 = weight[((size_t)o*CC + c0 + 9)*KK + kc] * s;
        __nv_bfloat162 h0 = __floats2bfloat162_rn(w0, w1);
        __nv_bfloat162 h1 = __floats2bfloat162_rn(w2, w3);
        __nv_bfloat162 l0 = __floats2bfloat162_rn(w0 - __bfloat162float(h0.x),
                                                  w1 - __bfloat162float(h0.y));
        __nv_bfloat162 l1 = __floats2bfloat162_rn(w2 - __bfloat162float(h1.x),
                                                  w3 - __bfloat162float(h1.y));
        uint4 v;
        v.x = *(uint32_t*)&h0;
        v.y = *(uint32_t*)&h1;
        v.z = *(uint32_t*)&l0;
        v.w = *(uint32_t*)&l1;
        g_wBf[idx] = v;
    } else if (idx < KK*4*8*32 + KK*4*4*32) {
        int idx2 = idx - KK*4*8*32;
        int T  = idx2 & 31;
        int nt = (idx2 >> 5) & 3;
        int kt = (idx2 >> 7) & 3;
        int kc = idx2 >> 9;
        int t = T & 3, g = T >> 2;
        int o = nt*8 + g;               // 0..31, valid j = 0..26
        int c0 = kt*16 + 2*t;
        float w0 = 0.f, w1 = 0.f, w2 = 0.f, w3 = 0.f;
        if (o < 27) {
            w0 = w_off[((size_t)o*CC + c0    )*KK + kc];
            w1 = w_off[((size_t)o*CC + c0 + 1)*KK + kc];
            w2 = w_off[((size_t)o*CC + c0 + 8)*KK + kc];
            w3 = w_off[((size_t)o*CC + c0 + 9)*KK + kc];
        }
        __nv_bfloat162 h0 = __floats2bfloat162_rn(w0, w1);
        __nv_bfloat162 h1 = __floats2bfloat162_rn(w2, w3);
        __nv_bfloat162 l0 = __floats2bfloat162_rn(w0 - __bfloat162float(h0.x),
                                                  w1 - __bfloat162float(h0.y));
        __nv_bfloat162 l1 = __floats2bfloat162_rn(w2 - __bfloat162float(h1.x),
                                                  w3 - __bfloat162float(h1.y));
        uint4 v;
        v.x = *(uint32_t*)&h0;
        v.y = *(uint32_t*)&h1;
        v.z = *(uint32_t*)&l0;
        v.w = *(uint32_t*)&l1;
        g_wOf[idx2] = v;
    }
}

// ---------------------------------------------------------------------------
// Kernel C (fused): offset conv (HMMA) + deformable sampling + main GEMM
// (HMMA) + BN bias + ReLU. One CTA per (b,h) row = 128 pixels, 8 warps x 16
// pixels, warps fully independent (NO __syncthreads).
//
// Phase 0 (per warp, per tap kc): build un-deformed A tile (1 float2 load per
//   (p, c-pair)), split-bf16 -> swizzled SMEM, 48 MMAs vs g_wOf -> raw
//   offsets/mask logits scattered into s_off[j][16].
// Phase 1 (per tap kc): bilinear gather+modulate -> split-bf16 A tile -> 96
//   MMAs vs g_wBf (kt-outer to keep fragment live range at 8 regs).
// SMEM: warp w: A tiles hi/lo at w*4096 (2KB each); s_off at 32768 + w*1792.
// ---------------------------------------------------------------------------
#define CT 256
#define SMEM_DCN (32768 + 8*1792)   // 47104 B

__global__ void __launch_bounds__(CT, 3) k_dcn(float* __restrict__ out,
                                               const float* __restrict__ b_off) {
    extern __shared__ char smem[];
    int tid = threadIdx.x;
    int wid = tid >> 5;
    int lane = tid & 31;
    int bh = blockIdx.x;
    int b = bh >> 7;
    int h = bh & (HH-1);
    int wp0 = wid * 16;                        // warp's first pixel (w coord)

    char* Ah = smem + wid*4096;
    char* Al = Ah + 2048;
    float* s_off = (float*)(smem + 32768 + wid*1792);

    int t = lane & 3, g = lane >> 2;
    const float* xb = g_x_nhwc + (size_t)b*HW*CC;
    const int c2 = 2*lane;

    // =================== Phase 0: offset conv via HMMA ===================
    {
        float acco[4][4];
#pragma unroll
        for (int nt = 0; nt < 4; nt++)
#pragma unroll
            for (int q = 0; q < 4; q++) acco[nt][q] = 0.f;

        for (int kc = 0; kc < 9; kc++) {
            int kr = kc/3 - 1, kx = kc%3 - 1;
            int yy = h + kr;
            bool vy = (yy >= 0) && (yy < HH);
            const float* xrow = xb + (size_t)(yy*WW)*CC + c2;
#pragma unroll 4
            for (int p = 0; p < 16; p++) {
                int xx = wp0 + p + kx;
                float ax = 0.f, ay = 0.f;
                if (vy && xx >= 0 && xx < WW) {
                    float2 v = *(const float2*)&xrow[(size_t)xx*CC];
                    ax = v.x; ay = v.y;
                }
                __nv_bfloat162 hp = __floats2bfloat162_rn(ax, ay);
                __nv_bfloat162 lp = __floats2bfloat162_rn(ax - __bfloat162float(hp.x),
                                                          ay - __bfloat162float(hp.y));
                uint32_t sw = (uint32_t)(lane*4) ^ (uint32_t)((p & 7) << 4);
                *(uint32_t*)(Ah + p*128 + sw) = *(uint32_t*)&hp;
                *(uint32_t*)(Al + p*128 + sw) = *(uint32_t*)&lp;
            }
            __syncwarp();
#pragma unroll
            for (int kt = 0; kt < 4; kt++) {
                uint32_t ah[4], al[4];
                uint32_t col0 = (uint32_t)(kt*32 + 4*t);
                uint32_t sw0 = col0 ^ (uint32_t)(g << 4);
                uint32_t sw2 = (col0 + 16) ^ (uint32_t)(g << 4);
                ah[0] = *(const uint32_t*)(Ah + g*128 + sw0);
                ah[1] = *(const uint32_t*)(Ah + (g+8)*128 + sw0);
                ah[2] = *(const uint32_t*)(Ah + g*128 + sw2);
                ah[3] = *(const uint32_t*)(Ah + (g+8)*128 + sw2);
                al[0] = *(const uint32_t*)(Al + g*128 + sw0);
                al[1] = *(const uint32_t*)(Al + (g+8)*128 + sw0);
                al[2] = *(const uint32_t*)(Al + g*128 + sw2);
                al[3] = *(const uint32_t*)(Al + (g+8)*128 + sw2);
                const uint4* wo = g_wOf + (size_t)kc*512 + kt*128 + lane;
#pragma unroll
                for (int nt = 0; nt < 4; nt++) {
                    uint4 bf = __ldg(wo + nt*32);
                    mma16816(acco[nt], ah, bf.x, bf.y);
                    mma16816(acco[nt], al, bf.x, bf.y);
                    mma16816(acco[nt], ah, bf.z, bf.w);
                }
            }
            __syncwarp();
        }
        // scatter raw offset/mask logits (+b_off) into s_off[j][16]
#pragma unroll
        for (int nt = 0; nt < 4; nt++) {
            int j0 = nt*8 + 2*t;
            if (j0 < 27) {
                float bo = __ldg(b_off + j0);
                s_off[j0*16 + g]     = acco[nt][0] + bo;
                s_off[j0*16 + g + 8] = acco[nt][2] + bo;
            }
            if (j0 + 1 < 27) {
                float bo = __ldg(b_off + j0 + 1);
                s_off[(j0+1)*16 + g]     = acco[nt][1] + bo;
                s_off[(j0+1)*16 + g + 8] = acco[nt][3] + bo;
            }
        }
        __syncwarp();
    }

    // =================== Phase 1: deformable conv via HMMA ===================
    float acc[8][4];
#pragma unroll
    for (int nt = 0; nt < 8; nt++)
#pragma unroll
        for (int q = 0; q < 4; q++) acc[nt][q] = 0.f;

    for (int kc = 0; kc < 9; kc++) {
        int kr = kc/3 - 1, kx = kc%3 - 1;
        // ---- gather + modulate + split-bf16 into swizzled A tile ----
#pragma unroll 2
        for (int p = 0; p < 16; p++) {
            float oy = s_off[(2*kc)*16 + p];
            float ox = s_off[(2*kc+1)*16 + p];
            float mv = 1.f / (1.f + __expf(-s_off[(18+kc)*16 + p]));
            float py = (float)(h + kr) + oy;
            float px = (float)(wp0 + p + kx) + ox;
            float y0f = floorf(py), x0f = floorf(px);
            float dy = py - y0f, dx = px - x0f;
            int y0 = (int)y0f, x0 = (int)x0f;
            int y1 = y0 + 1,  x1 = x0 + 1;
            bool vy0 = (y0 >= 0) && (y0 < HH);
            bool vy1 = (y1 >= 0) && (y1 < HH);
            bool vx0 = (x0 >= 0) && (x0 < WW);
            bool vx1 = (x1 >= 0) && (x1 < WW);
            float w00 = (1.f-dy)*(1.f-dx)*mv;
            float w01 = (1.f-dy)*dx*mv;
            float w10 = dy*(1.f-dx)*mv;
            float w11 = dy*dx*mv;

            float ax = 0.f, ay = 0.f;
            if (vy0 && vx0) {
                float2 v = *(const float2*)&xb[(y0*WW + x0)*CC + c2];
                ax = fmaf(w00, v.x, ax); ay = fmaf(w00, v.y, ay);
            }
            if (vy0 && vx1) {
                float2 v = *(const float2*)&xb[(y0*WW + x1)*CC + c2];
                ax = fmaf(w01, v.x, ax); ay = fmaf(w01, v.y, ay);
            }
            if (vy1 && vx0) {
                float2 v = *(const float2*)&xb[(y1*WW + x0)*CC + c2];
                ax = fmaf(w10, v.x, ax); ay = fmaf(w10, v.y, ay);
            }
            if (vy1 && vx1) {
                float2 v = *(const float2*)&xb[(y1*WW + x1)*CC + c2];
                ax = fmaf(w11, v.x, ax); ay = fmaf(w11, v.y, ay);
            }
            __nv_bfloat162 hp = __floats2bfloat162_rn(ax, ay);
            __nv_bfloat162 lp = __floats2bfloat162_rn(ax - __bfloat162float(hp.x),
                                                      ay - __bfloat162float(hp.y));
            uint32_t sw = (uint32_t)(lane*4) ^ (uint32_t)((p & 7) << 4);
            *(uint32_t*)(Ah + p*128 + sw) = *(uint32_t*)&hp;
            *(uint32_t*)(Al + p*128 + sw) = *(uint32_t*)&lp;
        }
        __syncwarp();

        // ---- kt-outer MMA: fragments live only inside kt iteration ----
        const uint4* wb = g_wBf + (size_t)kc*1024 + lane;
#pragma unroll
        for (int kt = 0; kt < 4; kt++) {
            uint32_t ah[4], al[4];
            uint32_t col0 = (uint32_t)(kt*32 + 4*t);
            uint32_t sw0 = col0 ^ (uint32_t)(g << 4);
            uint32_t sw2 = (col0 + 16) ^ (uint32_t)(g << 4);
            ah[0] = *(const uint32_t*)(Ah + g*128 + sw0);
            ah[1] = *(const uint32_t*)(Ah + (g+8)*128 + sw0);
            ah[2] = *(const uint32_t*)(Ah + g*128 + sw2);
            ah[3] = *(const uint32_t*)(Ah + (g+8)*128 + sw2);
            al[0] = *(const uint32_t*)(Al + g*128 + sw0);
            al[1] = *(const uint32_t*)(Al + (g+8)*128 + sw0);
            al[2] = *(const uint32_t*)(Al + g*128 + sw2);
            al[3] = *(const uint32_t*)(Al + (g+8)*128 + sw2);
#pragma unroll
            for (int nt = 0; nt < 8; nt++) {
                uint4 bf = __ldg(wb + (kt*8 + nt)*32);
                mma16816(acc[nt], ah, bf.x, bf.y);   // Ah*Bh
                mma16816(acc[nt], al, bf.x, bf.y);   // Al*Bh
                mma16816(acc[nt], ah, bf.z, bf.w);   // Ah*Bl
            }
        }
        __syncwarp();
    }

    // ---- epilogue: bias + ReLU, direct STG (NCHW) ----
    float* ob = out + (size_t)b*OC*HW + h*WW + wp0 + g;
#pragma unroll
    for (int nt = 0; nt < 8; nt++) {
        int n0 = nt*8 + 2*t;
        float b0 = __ldg(g_beff + n0);
        float b1 = __ldg(g_beff + n0 + 1);
        ob[(size_t)n0*HW]         = fmaxf(acc[nt][0] + b0, 0.f);
        ob[(size_t)(n0+1)*HW]     = fmaxf(acc[nt][1] + b1, 0.f);
        ob[(size_t)n0*HW + 8]     = fmaxf(acc[nt][2] + b0, 0.f);
        ob[(size_t)(n0+1)*HW + 8] = fmaxf(acc[nt][3] + b1, 0.f);
    }
}

// ---------------------------------------------------------------------------
extern "C" void kernel_launch(void* const* d_in, const int* in_sizes, int n_in,
                              void* d_out, int out_size) {
    const float* x      = (const float*)d_in[0];
    const float* w_off  = (const float*)d_in[1];
    const float* b_off  = (const float*)d_in[2];
    const float* weight = (const float*)d_in[3];
    const float* bias   = (const float*)d_in[4];
    const float* gamma  = (const float*)d_in[5];
    const float* beta   = (const float*)d_in[6];
    const float* rmean  = (const float*)d_in[7];
    const float* rvar   = (const float*)d_in[8];
    float* out = (float*)d_out;

    (void)in_sizes; (void)n_in; (void)out_size;

    cudaFuncSetAttribute(k_dcn, cudaFuncAttributeMaxDynamicSharedMemorySize, SMEM_DCN);

    k_transpose<<<BSZ*HH, TP_THREADS>>>(x);
    k_reorder<<<(KK*4*8*32 + KK*4*4*32 + 255)/256, 256>>>(weight, bias, gamma, beta,
                                                          rmean, rvar, w_off);
    k_dcn<<<BSZ*HH, CT, SMEM_DCN>>>(out, b_off);
}

// round 16
// speedup vs baseline: 3.0589x; 1.1406x over previous
#include <cuda_runtime.h>
#include <cuda_bf16.h>
#include <math.h>
#include <stdint.h>

// Problem constants
#define BSZ 4
#define CC  64
#define OC  64
#define HH  128
#define WW  128
#define HW  (HH*WW)        // 16384
#define KK  9
#define NPIX (BSZ*HW)      // 65536

// __device__ scratch (allocation-free rule: static device globals)
__device__ float g_x_nhwc[BSZ*HH*WW*CC];   // 16 MB, [b][h][w][c]
// Main conv weights in m16n8k16 B-fragment order, split-bf16:
// g_wBf[((kc*4 + kt)*8 + nt)*32 + lane] = {bh0, bh1, bl0, bl1}
__device__ uint4 g_wBf[KK*4*8*32];         // 147456 B
// Offset-conv weights, same fragment packing, N padded 27->32 (nt 0..3)
__device__ uint4 g_wOf[KK*4*4*32];         // 73728 B
__device__ float g_beff[OC];               // folded bias

// ---------------------------------------------------------------------------
// mma.sync m16n8k16 bf16 (PTX baseline, works under compute_103)
// ---------------------------------------------------------------------------
__device__ __forceinline__ void mma16816(float* c, const uint32_t* a,
                                         uint32_t b0, uint32_t b1) {
    asm volatile(
        "mma.sync.aligned.m16n8k16.row.col.f32.bf16.bf16.f32 "
        "{%0,%1,%2,%3}, {%4,%5,%6,%7}, {%8,%9}, {%0,%1,%2,%3};"
        : "+f"(c[0]), "+f"(c[1]), "+f"(c[2]), "+f"(c[3])
        : "r"(a[0]), "r"(a[1]), "r"(a[2]), "r"(a[3]), "r"(b0), "r"(b1));
}

// ---------------------------------------------------------------------------
// Kernel A: NCHW -> NHWC transpose of x, tiled through shared (conflict-free)
// ---------------------------------------------------------------------------
#define TP_THREADS 256
__global__ void k_transpose(const float* __restrict__ x) {
    __shared__ float tile[CC * (WW + 1)];
    int bh = blockIdx.x;
    int b = bh >> 7;
    int h = bh & (HH-1);
    const float* xp = x + ((size_t)(b*CC)*HH + h)*WW;
    for (int i = threadIdx.x; i < CC*WW; i += TP_THREADS) {
        int c = i >> 7;
        int w = i & (WW-1);
        tile[c*(WW+1) + w] = xp[(size_t)c*HW + w];
    }
    __syncthreads();
    float* op = g_x_nhwc + ((size_t)(b*HH + h)*WW)*CC;
    for (int i = threadIdx.x; i < CC*WW; i += TP_THREADS) {
        int c = i & (CC-1);
        int w = i >> 6;
        op[w*CC + c] = tile[c*(WW+1) + w];
    }
}

// ---------------------------------------------------------------------------
// Kernel R: fold BN into main weights + pack both weight sets into
// m16n8k16 B-fragment order (col-major B), split-bf16 hi/lo.
// ---------------------------------------------------------------------------
__global__ void k_reorder(const float* __restrict__ weight, const float* __restrict__ bias,
                          const float* __restrict__ gamma, const float* __restrict__ beta,
                          const float* __restrict__ rmean, const float* __restrict__ rvar,
                          const float* __restrict__ w_off) {
    int idx = blockIdx.x * blockDim.x + threadIdx.x;
    if (idx < OC) {
        float s = gamma[idx] * rsqrtf(rvar[idx] + 1e-5f);
        g_beff[idx] = (bias[idx] - rmean[idx]) * s + beta[idx];
    }
    if (idx < KK*4*8*32) {
        int T  = idx & 31;
        int nt = (idx >> 5) & 7;
        int kt = (idx >> 8) & 3;
        int kc = idx >> 10;
        int t = T & 3, g = T >> 2;
        int o = nt*8 + g;
        float s = gamma[o] * rsqrtf(rvar[o] + 1e-5f);
        int c0 = kt*16 + 2*t;
        float w0 = weight[((size_t)o*CC + c0    )*KK + kc] * s;
        float w1 = weight[((size_t)o*CC + c0 + 1)*KK + kc] * s;
        float w2 = weight[((size_t)o*CC + c0 + 8)*KK + kc] * s;
        float w3 = weight[((size_t)o*CC + c0 + 9)*KK + kc] * s;
        __nv_bfloat162 h0 = __floats2bfloat162_rn(w0, w1);
        __nv_bfloat162 h1 = __floats2bfloat162_rn(w2, w3);
        __nv_bfloat162 l0 = __floats2bfloat162_rn(w0 - __bfloat162float(h0.x),
                                                  w1 - __bfloat162float(h0.y));
        __nv_bfloat162 l1 = __floats2bfloat162_rn(w2 - __bfloat162float(h1.x),
                                                  w3 - __bfloat162float(h1.y));
        uint4 v;
        v.x = *(uint32_t*)&h0;
        v.y = *(uint32_t*)&h1;
        v.z = *(uint32_t*)&l0;
        v.w = *(uint32_t*)&l1;
        g_wBf[idx] = v;
    } else if (idx < KK*4*8*32 + KK*4*4*32) {
        int idx2 = idx - KK*4*8*32;
        int T  = idx2 & 31;
        int nt = (idx2 >> 5) & 3;
        int kt = (idx2 >> 7) & 3;
        int kc = idx2 >> 9;
        int t = T & 3, g = T >> 2;
        int o = nt*8 + g;               // 0..31, valid j = 0..26
        int c0 = kt*16 + 2*t;
        float w0 = 0.f, w1 = 0.f, w2 = 0.f, w3 = 0.f;
        if (o < 27) {
            w0 = w_off[((size_t)o*CC + c0    )*KK + kc];
            w1 = w_off[((size_t)o*CC + c0 + 1)*KK + kc];
            w2 = w_off[((size_t)o*CC + c0 + 8)*KK + kc];
            w3 = w_off[((size_t)o*CC + c0 + 9)*KK + kc];
        }
        __nv_bfloat162 h0 = __floats2bfloat162_rn(w0, w1);
        __nv_bfloat162 h1 = __floats2bfloat162_rn(w2, w3);
        __nv_bfloat162 l0 = __floats2bfloat162_rn(w0 - __bfloat162float(h0.x),
                                                  w1 - __bfloat162float(h0.y));
        __nv_bfloat162 l1 = __floats2bfloat162_rn(w2 - __bfloat162float(h1.x),
                                                  w3 - __bfloat162float(h1.y));
        uint4 v;
        v.x = *(uint32_t*)&h0;
        v.y = *(uint32_t*)&h1;
        v.z = *(uint32_t*)&l0;
        v.w = *(uint32_t*)&l1;
        g_wOf[idx2] = v;
    }
}

// ---------------------------------------------------------------------------
// Kernel C (fused): offset conv (HMMA) + deformable sampling + main GEMM
// (HMMA) + BN bias + ReLU. One CTA per (b,h) row = 128 pixels, 8 warps x 16
// pixels, warps fully independent (NO __syncthreads).
// __launch_bounds__(256,4): 592 CTA slots >= 512 grid -> SINGLE WAVE.
// ---------------------------------------------------------------------------
#define CT 256
#define SMEM_DCN (32768 + 8*1792)   // 47104 B  (x4 CTAs = 188 KB <= 227 KB)

__global__ void __launch_bounds__(CT, 4) k_dcn(float* __restrict__ out,
                                               const float* __restrict__ b_off) {
    extern __shared__ char smem[];
    int tid = threadIdx.x;
    int wid = tid >> 5;
    int lane = tid & 31;
    int bh = blockIdx.x;
    int b = bh >> 7;
    int h = bh & (HH-1);
    int wp0 = wid * 16;                        // warp's first pixel (w coord)

    char* Ah = smem + wid*4096;
    char* Al = Ah + 2048;
    float* s_off = (float*)(smem + 32768 + wid*1792);

    int t = lane & 3, g = lane >> 2;
    const float* xb = g_x_nhwc + (size_t)b*HW*CC;
    const int c2 = 2*lane;

    // =================== Phase 0: offset conv via HMMA ===================
    {
        float acco[4][4];
#pragma unroll
        for (int nt = 0; nt < 4; nt++)
#pragma unroll
            for (int q = 0; q < 4; q++) acco[nt][q] = 0.f;

        for (int kc = 0; kc < 9; kc++) {
            int kr = kc/3 - 1, kx = kc%3 - 1;
            int yy = h + kr;
            bool vy = (yy >= 0) && (yy < HH);
            const float* xrow = xb + (size_t)(yy*WW)*CC + c2;
#pragma unroll 2
            for (int p = 0; p < 16; p++) {
                int xx = wp0 + p + kx;
                float ax = 0.f, ay = 0.f;
                if (vy && xx >= 0 && xx < WW) {
                    float2 v = *(const float2*)&xrow[(size_t)xx*CC];
                    ax = v.x; ay = v.y;
                }
                __nv_bfloat162 hp = __floats2bfloat162_rn(ax, ay);
                __nv_bfloat162 lp = __floats2bfloat162_rn(ax - __bfloat162float(hp.x),
                                                          ay - __bfloat162float(hp.y));
                uint32_t sw = (uint32_t)(lane*4) ^ (uint32_t)((p & 7) << 4);
                *(uint32_t*)(Ah + p*128 + sw) = *(uint32_t*)&hp;
                *(uint32_t*)(Al + p*128 + sw) = *(uint32_t*)&lp;
            }
            __syncwarp();
#pragma unroll
            for (int kt = 0; kt < 4; kt++) {
                uint32_t ah[4], al[4];
                uint32_t col0 = (uint32_t)(kt*32 + 4*t);
                uint32_t sw0 = col0 ^ (uint32_t)(g << 4);
                uint32_t sw2 = (col0 + 16) ^ (uint32_t)(g << 4);
                ah[0] = *(const uint32_t*)(Ah + g*128 + sw0);
                ah[1] = *(const uint32_t*)(Ah + (g+8)*128 + sw0);
                ah[2] = *(const uint32_t*)(Ah + g*128 + sw2);
                ah[3] = *(const uint32_t*)(Ah + (g+8)*128 + sw2);
                al[0] = *(const uint32_t*)(Al + g*128 + sw0);
                al[1] = *(const uint32_t*)(Al + (g+8)*128 + sw0);
                al[2] = *(const uint32_t*)(Al + g*128 + sw2);
                al[3] = *(const uint32_t*)(Al + (g+8)*128 + sw2);
                const uint4* wo = g_wOf + (size_t)kc*512 + kt*128 + lane;
#pragma unroll
                for (int nt = 0; nt < 4; nt++) {
                    uint4 bf = __ldg(wo + nt*32);
                    mma16816(acco[nt], ah, bf.x, bf.y);
                    mma16816(acco[nt], al, bf.x, bf.y);
                    mma16816(acco[nt], ah, bf.z, bf.w);
                }
            }
            __syncwarp();
        }
        // scatter raw offset/mask logits (+b_off) into s_off[j][16]
#pragma unroll
        for (int nt = 0; nt < 4; nt++) {
            int j0 = nt*8 + 2*t;
            if (j0 < 27) {
                float bo = __ldg(b_off + j0);
                s_off[j0*16 + g]     = acco[nt][0] + bo;
                s_off[j0*16 + g + 8] = acco[nt][2] + bo;
            }
            if (j0 + 1 < 27) {
                float bo = __ldg(b_off + j0 + 1);
                s_off[(j0+1)*16 + g]     = acco[nt][1] + bo;
                s_off[(j0+1)*16 + g + 8] = acco[nt][3] + bo;
            }
        }
        __syncwarp();
    }

    // =================== Phase 1: deformable conv via HMMA ===================
    float acc[8][4];
#pragma unroll
    for (int nt = 0; nt < 8; nt++)
#pragma unroll
        for (int q = 0; q < 4; q++) acc[nt][q] = 0.f;

    for (int kc = 0; kc < 9; kc++) {
        int kr = kc/3 - 1, kx = kc%3 - 1;
        // ---- gather + modulate + split-bf16 into swizzled A tile ----
#pragma unroll 1
        for (int p = 0; p < 16; p++) {
            float oy = s_off[(2*kc)*16 + p];
            float ox = s_off[(2*kc+1)*16 + p];
            float mv = 1.f / (1.f + __expf(-s_off[(18+kc)*16 + p]));
            float py = (float)(h + kr) + oy;
            float px = (float)(wp0 + p + kx) + ox;
            float y0f = floorf(py), x0f = floorf(px);
            float dy = py - y0f, dx = px - x0f;
            int y0 = (int)y0f, x0 = (int)x0f;
            int y1 = y0 + 1,  x1 = x0 + 1;
            bool vy0 = (y0 >= 0) && (y0 < HH);
            bool vy1 = (y1 >= 0) && (y1 < HH);
            bool vx0 = (x0 >= 0) && (x0 < WW);
            bool vx1 = (x1 >= 0) && (x1 < WW);
            float w00 = (1.f-dy)*(1.f-dx)*mv;
            float w01 = (1.f-dy)*dx*mv;
            float w10 = dy*(1.f-dx)*mv;
            float w11 = dy*dx*mv;

            float ax = 0.f, ay = 0.f;
            if (vy0 && vx0) {
                float2 v = *(const float2*)&xb[(y0*WW + x0)*CC + c2];
                ax = fmaf(w00, v.x, ax); ay = fmaf(w00, v.y, ay);
            }
            if (vy0 && vx1) {
                float2 v = *(const float2*)&xb[(y0*WW + x1)*CC + c2];
                ax = fmaf(w01, v.x, ax); ay = fmaf(w01, v.y, ay);
            }
            if (vy1 && vx0) {
                float2 v = *(const float2*)&xb[(y1*WW + x0)*CC + c2];
                ax = fmaf(w10, v.x, ax); ay = fmaf(w10, v.y, ay);
            }
            if (vy1 && vx1) {
                float2 v = *(const float2*)&xb[(y1*WW + x1)*CC + c2];
                ax = fmaf(w11, v.x, ax); ay = fmaf(w11, v.y, ay);
            }
            __nv_bfloat162 hp = __floats2bfloat162_rn(ax, ay);
            __nv_bfloat162 lp = __floats2bfloat162_rn(ax - __bfloat162float(hp.x),
                                                      ay - __bfloat162float(hp.y));
            uint32_t sw = (uint32_t)(lane*4) ^ (uint32_t)((p & 7) << 4);
            *(uint32_t*)(Ah + p*128 + sw) = *(uint32_t*)&hp;
            *(uint32_t*)(Al + p*128 + sw) = *(uint32_t*)&lp;
        }
        __syncwarp();

        // ---- kt-outer MMA: fragments live only inside kt iteration ----
        const uint4* wb = g_wBf + (size_t)kc*1024 + lane;
#pragma unroll
        for (int kt = 0; kt < 4; kt++) {
            uint32_t ah[4], al[4];
            uint32_t col0 = (uint32_t)(kt*32 + 4*t);
            uint32_t sw0 = col0 ^ (uint32_t)(g << 4);
            uint32_t sw2 = (col0 + 16) ^ (uint32_t)(g << 4);
            ah[0] = *(const uint32_t*)(Ah + g*128 + sw0);
            ah[1] = *(const uint32_t*)(Ah + (g+8)*128 + sw0);
            ah[2] = *(const uint32_t*)(Ah + g*128 + sw2);
            ah[3] = *(const uint32_t*)(Ah + (g+8)*128 + sw2);
            al[0] = *(const uint32_t*)(Al + g*128 + sw0);
            al[1] = *(const uint32_t*)(Al + (g+8)*128 + sw0);
            al[2] = *(const uint32_t*)(Al + g*128 + sw2);
            al[3] = *(const uint32_t*)(Al + (g+8)*128 + sw2);
#pragma unroll
            for (int nt = 0; nt < 8; nt++) {
                uint4 bf = __ldg(wb + (kt*8 + nt)*32);
                mma16816(acc[nt], ah, bf.x, bf.y);   // Ah*Bh
                mma16816(acc[nt], al, bf.x, bf.y);   // Al*Bh
                mma16816(acc[nt], ah, bf.z, bf.w);   // Ah*Bl
            }
        }
        __syncwarp();
    }

    // ---- epilogue: bias + ReLU, direct STG (NCHW) ----
    float* ob = out + (size_t)b*OC*HW + h*WW + wp0 + g;
#pragma unroll
    for (int nt = 0; nt < 8; nt++) {
        int n0 = nt*8 + 2*t;
        float b0 = __ldg(g_beff + n0);
        float b1 = __ldg(g_beff + n0 + 1);
        ob[(size_t)n0*HW]         = fmaxf(acc[nt][0] + b0, 0.f);
        ob[(size_t)(n0+1)*HW]     = fmaxf(acc[nt][1] + b1, 0.f);
        ob[(size_t)n0*HW + 8]     = fmaxf(acc[nt][2] + b0, 0.f);
        ob[(size_t)(n0+1)*HW + 8] = fmaxf(acc[nt][3] + b1, 0.f);
    }
}

// ---------------------------------------------------------------------------
extern "C" void kernel_launch(void* const* d_in, const int* in_sizes, int n_in,
                              void* d_out, int out_size) {
    const float* x      = (const float*)d_in[0];
    const float* w_off  = (const float*)d_in[1];
    const float* b_off  = (const float*)d_in[2];
    const float* weight = (const float*)d_in[3];
    const float* bias   = (const float*)d_in[4];
    const float* gamma  = (const float*)d_in[5];
    const float* beta   = (const float*)d_in[6];
    const float* rmean  = (const float*)d_in[7];
    const float* rvar   = (const float*)d_in[8];
    float* out = (float*)d_out;

    (void)in_sizes; (void)n_in; (void)out_size;

    cudaFuncSetAttribute(k_dcn, cudaFuncAttributeMaxDynamicSharedMemorySize, SMEM_DCN);

    k_transpose<<<BSZ*HH, TP_THREADS>>>(x);
    k_reorder<<<(KK*4*8*32 + KK*4*4*32 + 255)/256, 256>>>(weight, bias, gamma, beta,
                                                          rmean, rvar, w_off);
    k_dcn<<<BSZ*HH, CT, SMEM_DCN>>>(out, b_off);
}